// round 7
// baseline (speedup 1.0000x reference)
#include <cuda_runtime.h>
#include <stdint.h>

// PackBits: word w has bit p = signbit(x[32*w + (p^7)])
//   (numpy packbits MSB-first per byte + little-endian uint32 view
//    => element k lands at bit position k^7 within its word.)
//
// Harness readback is float-valued with the reference uint32 words
// reinterpreted as SIGNED int32 (rel_err was exactly sqrt(6) when we wrote
// unsigned values => off by 2^32 on exactly the bit31-set half). So we store
// (float)(int32)word.
//
// Scheme: lane l loads element 32*w + (l^7) -> warp load = one 128B row
//         (the ^7 permutes within 8-lane groups; sectors unchanged).
//         __ballot_sync((int)v < 0) IS the packed word (bit p = lane p).
//         Each warp makes WPW=32 consecutive words; ballot j's uniform result
//         is kept by lane j, then one coalesced 128B store.

#define WPW 32  // words per warp

__global__ __launch_bounds__(256) void packbits_kernel(
    const unsigned int* __restrict__ x,  // fp32 bits: sign = bit 31
    float* __restrict__ out,
    int nwords, long long nelem)
{
    const int lane = threadIdx.x & 31;
    const long long warp_global = (long long)((blockIdx.x * blockDim.x + threadIdx.x) >> 5);
    const long long word0 = warp_global * WPW;
    if (word0 >= nwords) return;

    const int src_lane = lane ^ 7;

    if (word0 + WPW <= (long long)nwords && (word0 + WPW) * 32 <= nelem) {
        // Fast path: full tile.
        const unsigned int* p = x + word0 * 32 + src_lane;
        unsigned int mine = 0;
#pragma unroll
        for (int j = 0; j < WPW; j++) {
            unsigned int v = p[(long long)j * 32];
            unsigned int w = __ballot_sync(0xFFFFFFFFu, (int)v < 0);
            if (lane == j) mine = w;
        }
        out[word0 + lane] = (float)(int)mine;   // signed reinterpret, then RN cast
    } else {
        // Tail path (not hit for N=2^27; kept for generality).
        for (int j = 0; j < WPW; j++) {
            long long wi = word0 + j;
            if (wi >= nwords) break;
            long long idx = wi * 32 + src_lane;
            unsigned int v = (idx < nelem) ? x[idx] : 0u;
            unsigned int w = __ballot_sync(0xFFFFFFFFu, (int)v < 0);
            if (lane == 0) out[wi] = (float)(int)w;
        }
    }
}

extern "C" void kernel_launch(void* const* d_in, const int* in_sizes, int n_in,
                              void* d_out, int out_size)
{
    const unsigned int* x = (const unsigned int*)d_in[0];
    float* out = (float*)d_out;
    long long n = (long long)in_sizes[0];
    int nwords = out_size;  // ceil(n/32); here n = 2^27 -> nwords = 2^22

    const int threads = 256;                           // 8 warps/block
    const int words_per_block = (threads / 32) * WPW;  // 256 words/block
    int blocks = (int)((nwords + (long long)words_per_block - 1) / words_per_block);

    packbits_kernel<<<blocks, threads>>>(x, out, nwords, n);
}

// round 8
// speedup vs baseline: 1.0780x; 1.0780x over previous
#include <cuda_runtime.h>
#include <stdint.h>

// PackBits: word w has bit p = signbit(x[32*w + (p^7)])
//   (numpy packbits MSB-first per byte + little-endian uint32 view
//    => element k lands at bit position k^7 within its word.)
// Harness readback: reference uint32 words reinterpreted as SIGNED int32,
// value-compared in float64 -> we store (float)(int32)word.
//
// Scheme: lane l loads element 32*w + (l^7) -> warp load = one 128B row
//         (^7 permutes within 8-lane groups; sector pattern unchanged).
//         __ballot_sync((int)v < 0) IS the packed word (bit p = lane p).
//         Each warp makes WPW=32 consecutive words; ballot j's uniform result
//         is kept by lane j, then one coalesced 128B store.
//
// R8 change: two-phase body. Phase 1 issues ALL 32 LDGs into a register
// array (guaranteed MLP=32 per warp; previous fused loop at regs=31 forced
// ptxas to interleave load->vote, serializing on the warp-wide ballot).
// Phase 2 runs the 32 ballots on register-resident values. Streaming cache
// hints (__ldcs/__stcs) since neither input nor output is ever reused.

#define WPW 32  // words per warp

__global__ __launch_bounds__(256) void packbits_kernel(
    const unsigned int* __restrict__ x,  // fp32 bits: sign = bit 31
    float* __restrict__ out,
    int nwords, long long nelem)
{
    const int lane = threadIdx.x & 31;
    const long long warp_global = (long long)((blockIdx.x * blockDim.x + threadIdx.x) >> 5);
    const long long word0 = warp_global * WPW;
    if (word0 >= nwords) return;

    const int src_lane = lane ^ 7;

    if (word0 + WPW <= (long long)nwords && (word0 + WPW) * 32 <= nelem) {
        // Fast path: full tile.
        const unsigned int* p = x + word0 * 32 + src_lane;

        // Phase 1: batch all loads -> MLP = 32 in flight per warp.
        unsigned int v[WPW];
#pragma unroll
        for (int j = 0; j < WPW; j++)
            v[j] = __ldcs(p + (long long)j * 32);

        // Phase 2: ballots on register-resident values.
        unsigned int mine = 0;
#pragma unroll
        for (int j = 0; j < WPW; j++) {
            unsigned int w = __ballot_sync(0xFFFFFFFFu, (int)v[j] < 0);
            if (lane == j) mine = w;
        }
        __stcs(&out[word0 + lane], (float)(int)mine);  // coalesced 128B row
    } else {
        // Tail path (not hit for N=2^27; kept for generality).
        for (int j = 0; j < WPW; j++) {
            long long wi = word0 + j;
            if (wi >= nwords) break;
            long long idx = wi * 32 + src_lane;
            unsigned int v = (idx < nelem) ? x[idx] : 0u;
            unsigned int w = __ballot_sync(0xFFFFFFFFu, (int)v < 0);
            if (lane == 0) out[wi] = (float)(int)w;
        }
    }
}

extern "C" void kernel_launch(void* const* d_in, const int* in_sizes, int n_in,
                              void* d_out, int out_size)
{
    const unsigned int* x = (const unsigned int*)d_in[0];
    float* out = (float*)d_out;
    long long n = (long long)in_sizes[0];
    int nwords = out_size;  // ceil(n/32); here n = 2^27 -> nwords = 2^22

    const int threads = 256;                           // 8 warps/block
    const int words_per_block = (threads / 32) * WPW;  // 256 words/block
    int blocks = (int)((nwords + (long long)words_per_block - 1) / words_per_block);

    packbits_kernel<<<blocks, threads>>>(x, out, nwords, n);
}